// round 1
// baseline (speedup 1.0000x reference)
#include <cuda_runtime.h>

#define N_TOK 8192
#define HID   2048
#define NE    8

// gate probabilities [N_TOK, NE] — static device scratch (no allocation)
__device__ float g_gate[N_TOK * NE];

// ---------------------------------------------------------------------------
// Gate kernel: one warp per token. logits = x @ Wg + bg, softmax over 8.
// ---------------------------------------------------------------------------
__global__ __launch_bounds__(256) void gate_kernel(const float* __restrict__ x,
                                                   const float* __restrict__ Wg,
                                                   const float* __restrict__ bg) {
    int warp = (blockIdx.x * blockDim.x + threadIdx.x) >> 5;
    int lane = threadIdx.x & 31;
    if (warp >= N_TOK) return;

    const float* xr = x + (size_t)warp * HID;
    float acc[NE];
#pragma unroll
    for (int e = 0; e < NE; e++) acc[e] = 0.f;

    // each lane strides over K in float4 chunks
    for (int k0 = lane * 4; k0 < HID; k0 += 128) {
        float4 xv = *(const float4*)(xr + k0);
        float xs[4] = {xv.x, xv.y, xv.z, xv.w};
        const float* wr = Wg + (size_t)k0 * NE;
#pragma unroll
        for (int r = 0; r < 4; r++) {
            float4 w0 = *(const float4*)(wr + r * NE);
            float4 w1 = *(const float4*)(wr + r * NE + 4);
            acc[0] += xs[r] * w0.x;  acc[1] += xs[r] * w0.y;
            acc[2] += xs[r] * w0.z;  acc[3] += xs[r] * w0.w;
            acc[4] += xs[r] * w1.x;  acc[5] += xs[r] * w1.y;
            acc[6] += xs[r] * w1.z;  acc[7] += xs[r] * w1.w;
        }
    }
    // warp reduce all 8 sums (every lane ends with the totals)
#pragma unroll
    for (int e = 0; e < NE; e++) {
#pragma unroll
        for (int o = 16; o; o >>= 1)
            acc[e] += __shfl_xor_sync(0xFFFFFFFFu, acc[e], o);
    }
    if (lane == 0) {
#pragma unroll
        for (int e = 0; e < NE; e++) acc[e] += bg[e];
        float m = acc[0];
#pragma unroll
        for (int e = 1; e < NE; e++) m = fmaxf(m, acc[e]);
        float s = 0.f;
        float p[NE];
#pragma unroll
        for (int e = 0; e < NE; e++) { p[e] = __expf(acc[e] - m); s += p[e]; }
        float inv = 1.f / s;
        float4 o0 = make_float4(p[0]*inv, p[1]*inv, p[2]*inv, p[3]*inv);
        float4 o1 = make_float4(p[4]*inv, p[5]*inv, p[6]*inv, p[7]*inv);
        float* gp = &g_gate[(size_t)warp * NE];
        *(float4*)(gp)     = o0;
        *(float4*)(gp + 4) = o1;
    }
}

// ---------------------------------------------------------------------------
// Main fused kernel: for each 128x128 (token, feature) tile, loop over the 8
// experts; per expert a BK=8 double-buffered SGEMM panel, then epilogue
//   out += gate[n,e] * ( relu(acc + b[e,f]) + cached[e,f] )
// e==0 writes (output is poisoned), e>0 read-modify-writes. Each thread only
// touches its own 64 output elements, so no cross-thread hazards.
// ---------------------------------------------------------------------------
__global__ __launch_bounds__(256, 2)
void moe_main_kernel(const float* __restrict__ x,
                     const float* __restrict__ W,
                     const float* __restrict__ b,
                     const float* __restrict__ cached,
                     float* __restrict__ out) {
    __shared__ float As[2][8][128];   // [buf][k][m] (transposed A)
    __shared__ float Bs[2][8][128];   // [buf][k][n]

    const int tid = threadIdx.x;
    const int tx  = tid & 15;         // 0..15 -> column groups
    const int ty  = tid >> 4;         // 0..15 -> row groups
    const int n0  = blockIdx.y * 128; // token tile
    const int f0  = blockIdx.x * 128; // feature tile

    // global->smem load mapping
    const int arow = tid >> 1;          // 0..127
    const int acol = (tid & 1) * 4;     // 0 or 4
    const int brow = tid >> 5;          // 0..7
    const int bcol = (tid & 31) * 4;    // 0..124

    const float* xA = x + (size_t)(n0 + arow) * HID + acol;

    const int r0 = ty * 4;   // rows r0..r0+3 and 64+r0..64+r0+3
    const int c0 = tx * 4;   // cols c0..c0+3 and 64+c0..64+c0+3

    for (int e = 0; e < NE; e++) {
        const float* Be = W + (size_t)e * HID * HID + f0;

        float acc[8][8];
#pragma unroll
        for (int i = 0; i < 8; i++)
#pragma unroll
            for (int j = 0; j < 8; j++) acc[i][j] = 0.f;

        // preload k-tile 0 into buffer 0
        {
            float4 av = *(const float4*)(xA);
            float4 bv = *(const float4*)(Be + (size_t)brow * HID + bcol);
            As[0][acol + 0][arow] = av.x;
            As[0][acol + 1][arow] = av.y;
            As[0][acol + 2][arow] = av.z;
            As[0][acol + 3][arow] = av.w;
            *(float4*)&Bs[0][brow][bcol] = bv;
        }
        __syncthreads();

        int buf = 0;
        const int NKT = HID / 8;  // 256
        for (int kt = 0; kt < NKT; kt++) {
            float4 av2, bv2;
            const bool has_next = (kt + 1 < NKT);
            if (has_next) {
                int kn = (kt + 1) * 8;
                av2 = *(const float4*)(xA + kn);
                bv2 = *(const float4*)(Be + (size_t)(kn + brow) * HID + bcol);
            }
#pragma unroll
            for (int kk = 0; kk < 8; kk++) {
                float a[8], bb[8];
                *(float4*)&a[0]  = *(const float4*)&As[buf][kk][r0];
                *(float4*)&a[4]  = *(const float4*)&As[buf][kk][r0 + 64];
                *(float4*)&bb[0] = *(const float4*)&Bs[buf][kk][c0];
                *(float4*)&bb[4] = *(const float4*)&Bs[buf][kk][c0 + 64];
#pragma unroll
                for (int i = 0; i < 8; i++)
#pragma unroll
                    for (int j = 0; j < 8; j++)
                        acc[i][j] = fmaf(a[i], bb[j], acc[i][j]);
            }
            if (has_next) {
                int nb = buf ^ 1;
                As[nb][acol + 0][arow] = av2.x;
                As[nb][acol + 1][arow] = av2.y;
                As[nb][acol + 2][arow] = av2.z;
                As[nb][acol + 3][arow] = av2.w;
                *(float4*)&Bs[nb][brow][bcol] = bv2;
            }
            __syncthreads();
            buf ^= 1;
        }

        // ---- epilogue for expert e ----
        const float* be = b      + (size_t)e * HID + f0;
        const float* ce = cached + (size_t)e * HID + f0;
        float bias[8], cch[8];
        *(float4*)&bias[0] = *(const float4*)(be + c0);
        *(float4*)&bias[4] = *(const float4*)(be + c0 + 64);
        *(float4*)&cch[0]  = *(const float4*)(ce + c0);
        *(float4*)&cch[4]  = *(const float4*)(ce + c0 + 64);

#pragma unroll
        for (int i = 0; i < 8; i++) {
            const int row = n0 + ((i < 4) ? (r0 + i) : (64 + r0 + i - 4));
            const float g = g_gate[(size_t)row * NE + e];
            float* orow = out + (size_t)row * HID + f0;
#pragma unroll
            for (int jj = 0; jj < 2; jj++) {
                const int cc = (jj == 0) ? c0 : (c0 + 64);
                float4 v;
                v.x = g * (fmaxf(acc[i][jj*4 + 0] + bias[jj*4 + 0], 0.f) + cch[jj*4 + 0]);
                v.y = g * (fmaxf(acc[i][jj*4 + 1] + bias[jj*4 + 1], 0.f) + cch[jj*4 + 1]);
                v.z = g * (fmaxf(acc[i][jj*4 + 2] + bias[jj*4 + 2], 0.f) + cch[jj*4 + 2]);
                v.w = g * (fmaxf(acc[i][jj*4 + 3] + bias[jj*4 + 3], 0.f) + cch[jj*4 + 3]);
                if (e == 0) {
                    *(float4*)(orow + cc) = v;
                } else {
                    float4 o = *(const float4*)(orow + cc);
                    o.x += v.x; o.y += v.y; o.z += v.z; o.w += v.w;
                    *(float4*)(orow + cc) = o;
                }
            }
        }
        // k-loop ended with a __syncthreads(); next expert's preload is safe.
    }
}

// ---------------------------------------------------------------------------
// Launch
// inputs (metadata order): x[8192*2048], W[8*2048*2048], b[8*2048],
//                          Wg[2048*8], bg[8], cached[8*2048]
// ---------------------------------------------------------------------------
extern "C" void kernel_launch(void* const* d_in, const int* in_sizes, int n_in,
                              void* d_out, int out_size) {
    const float* x      = (const float*)d_in[0];
    const float* W      = (const float*)d_in[1];
    const float* b      = (const float*)d_in[2];
    const float* Wg     = (const float*)d_in[3];
    const float* bg     = (const float*)d_in[4];
    const float* cached = (const float*)d_in[5];
    float* out = (float*)d_out;

    // gate: one warp per token, 8 warps per block
    gate_kernel<<<N_TOK / 8, 256>>>(x, Wg, bg);

    // main fused MoE GEMM
    dim3 grid(HID / 128, N_TOK / 128);  // (16, 64)
    moe_main_kernel<<<grid, 256>>>(x, W, b, cached, out);
}

// round 3
// speedup vs baseline: 1.7194x; 1.7194x over previous
#include <cuda_runtime.h>
#include <cuda_bf16.h>
#include <cstdint>

#define N_TOK 8192
#define HID   2048
#define NE    8

// ---------------------------------------------------------------------------
// Static device scratch
// ---------------------------------------------------------------------------
__device__ float          g_gate[N_TOK * NE];
__device__ __nv_bfloat16  g_xhi [(size_t)N_TOK * HID];
__device__ __nv_bfloat16  g_xlo [(size_t)N_TOK * HID];
__device__ __nv_bfloat16  g_wthi[(size_t)NE * HID * HID];   // W^T hi  [e][f][h]
__device__ __nv_bfloat16  g_wtlo[(size_t)NE * HID * HID];   // W^T lo

// ---------------------------------------------------------------------------
// PTX helpers (all baseline sm_80/75-era — no arch-suffix instructions)
// ---------------------------------------------------------------------------
__device__ __forceinline__ uint32_t smem_u32(const void* p) {
    uint32_t a;
    asm("{ .reg .u64 t; cvta.to.shared.u64 t, %1; cvt.u32.u64 %0, t; }"
        : "=r"(a) : "l"(p));
    return a;
}
#define CP16(dst, src) \
    asm volatile("cp.async.cg.shared.global [%0], [%1], 16;" \
                 :: "r"(dst), "l"(src) : "memory")
#define CP_COMMIT() asm volatile("cp.async.commit_group;" ::: "memory")
#define CP_WAIT(n)  asm volatile("cp.async.wait_group %0;" :: "n"(n) : "memory")

#define LDSM_X4(r0, r1, r2, r3, a) \
    asm volatile("ldmatrix.sync.aligned.m8n8.x4.shared.b16 {%0,%1,%2,%3}, [%4];" \
                 : "=r"(r0), "=r"(r1), "=r"(r2), "=r"(r3) : "r"(a))

__device__ __forceinline__ void mma16816(float* d, const uint32_t* a,
                                         const uint32_t* bfr) {
    asm volatile(
        "mma.sync.aligned.m16n8k16.row.col.f32.bf16.bf16.f32 "
        "{%0,%1,%2,%3}, {%4,%5,%6,%7}, {%8,%9}, {%0,%1,%2,%3};"
        : "+f"(d[0]), "+f"(d[1]), "+f"(d[2]), "+f"(d[3])
        : "r"(a[0]), "r"(a[1]), "r"(a[2]), "r"(a[3]), "r"(bfr[0]), "r"(bfr[1]));
}

// ---------------------------------------------------------------------------
// Gate kernel (one warp per token): softmax(x @ Wg + bg)
// ---------------------------------------------------------------------------
__global__ __launch_bounds__(256) void gate_kernel(const float* __restrict__ x,
                                                   const float* __restrict__ Wg,
                                                   const float* __restrict__ bg) {
    int warp = (blockIdx.x * blockDim.x + threadIdx.x) >> 5;
    int lane = threadIdx.x & 31;
    if (warp >= N_TOK) return;
    const float* xr = x + (size_t)warp * HID;
    float acc[NE];
#pragma unroll
    for (int e = 0; e < NE; e++) acc[e] = 0.f;
    for (int k0 = lane * 4; k0 < HID; k0 += 128) {
        float4 xv = *(const float4*)(xr + k0);
        float xs[4] = {xv.x, xv.y, xv.z, xv.w};
        const float* wr = Wg + (size_t)k0 * NE;
#pragma unroll
        for (int r = 0; r < 4; r++) {
            float4 w0 = *(const float4*)(wr + r * NE);
            float4 w1 = *(const float4*)(wr + r * NE + 4);
            acc[0] += xs[r] * w0.x;  acc[1] += xs[r] * w0.y;
            acc[2] += xs[r] * w0.z;  acc[3] += xs[r] * w0.w;
            acc[4] += xs[r] * w1.x;  acc[5] += xs[r] * w1.y;
            acc[6] += xs[r] * w1.z;  acc[7] += xs[r] * w1.w;
        }
    }
#pragma unroll
    for (int e = 0; e < NE; e++)
#pragma unroll
        for (int o = 16; o; o >>= 1)
            acc[e] += __shfl_xor_sync(0xFFFFFFFFu, acc[e], o);
    if (lane == 0) {
#pragma unroll
        for (int e = 0; e < NE; e++) acc[e] += bg[e];
        float m = acc[0];
#pragma unroll
        for (int e = 1; e < NE; e++) m = fmaxf(m, acc[e]);
        float s = 0.f, p[NE];
#pragma unroll
        for (int e = 0; e < NE; e++) { p[e] = __expf(acc[e] - m); s += p[e]; }
        float inv = 1.f / s;
        float* gp = &g_gate[(size_t)warp * NE];
        *(float4*)(gp)     = make_float4(p[0]*inv, p[1]*inv, p[2]*inv, p[3]*inv);
        *(float4*)(gp + 4) = make_float4(p[4]*inv, p[5]*inv, p[6]*inv, p[7]*inv);
    }
}

// ---------------------------------------------------------------------------
// Split x into bf16 hi/lo
// ---------------------------------------------------------------------------
__global__ __launch_bounds__(256) void split_x_kernel(const float* __restrict__ x) {
    size_t i = ((size_t)blockIdx.x * blockDim.x + threadIdx.x) * 8;
    float4 a = *(const float4*)(x + i);
    float4 c = *(const float4*)(x + i + 4);
    float v[8] = {a.x, a.y, a.z, a.w, c.x, c.y, c.z, c.w};
    __align__(16) __nv_bfloat16 h[8], l[8];
#pragma unroll
    for (int j = 0; j < 8; j++) {
        h[j] = __float2bfloat16(v[j]);
        l[j] = __float2bfloat16(v[j] - __bfloat162float(h[j]));
    }
    *(uint4*)&g_xhi[i] = *(uint4*)h;
    *(uint4*)&g_xlo[i] = *(uint4*)l;
}

// ---------------------------------------------------------------------------
// Transpose + split W: W[e,h,f] fp32 -> Wt[e,f,h] bf16 hi/lo
// ---------------------------------------------------------------------------
__global__ __launch_bounds__(256) void transpose_split_w(const float* __restrict__ W) {
    __shared__ float tile[32][33];
    const int e  = blockIdx.z;
    const int h0 = blockIdx.y * 32;
    const int f0 = blockIdx.x * 32;
    const int tx = threadIdx.x & 31;
    const int ty = threadIdx.x >> 5;
#pragma unroll
    for (int i = 0; i < 32; i += 8)
        tile[ty + i][tx] = W[((size_t)e * HID + h0 + ty + i) * HID + f0 + tx];
    __syncthreads();
#pragma unroll
    for (int i = 0; i < 32; i += 8) {
        float v = tile[tx][ty + i];
        __nv_bfloat16 hi = __float2bfloat16(v);
        __nv_bfloat16 lo = __float2bfloat16(v - __bfloat162float(hi));
        size_t di = ((size_t)e * HID + f0 + ty + i) * HID + h0 + tx;
        g_wthi[di] = hi;
        g_wtlo[di] = lo;
    }
}

// ---------------------------------------------------------------------------
// Main mma.sync kernel.
// CTA: 128x128 tile. 8 warps (2x4), warp tile 64x32, bf16x3 split, BK=32,
// cp.async double-buffered smem with 80B row stride (conflict-free ldmatrix).
// Expert loop fused into one pipeline; epilogue per expert RMWs out.
// ---------------------------------------------------------------------------
#define BK 32
#define ROWB 80                       // padded row stride (bytes) for 64B rows
#define TILE_B (128 * ROWB)           // 10240
#define STAGE_B (4 * TILE_B)          // 40960: A_hi, A_lo, B_hi, B_lo
#define SMEM_MAIN (2 * STAGE_B)       // 81920
#define ITERS_PER_E (HID / BK)        // 64
#define TOT_ITERS (NE * ITERS_PER_E)  // 512

__global__ __launch_bounds__(256, 2)
void moe_mma_kernel(const float* __restrict__ bias,
                    const float* __restrict__ cached,
                    float* __restrict__ out) {
    extern __shared__ char sm[];
    const uint32_t sbase = smem_u32(sm);

    const int tid  = threadIdx.x;
    const int wid  = tid >> 5;
    const int lane = tid & 31;
    const int n0 = blockIdx.y * 128;
    const int f0 = blockIdx.x * 128;
    const int warp_m = wid >> 2;      // 0..1
    const int warp_n = wid & 3;       // 0..3

    // ---- global->smem load mapping (per thread: 32B from one row per tile)
    const int lr = tid & 127;         // row 0..127
    const int lh = tid >> 7;          // half 0..1 (16 bf16 = 32B)
    const __nv_bfloat16* srcAh = g_xhi + (size_t)(n0 + lr) * HID + lh * 16;
    const __nv_bfloat16* srcAl = g_xlo + (size_t)(n0 + lr) * HID + lh * 16;
    const size_t bRowOff = (size_t)(f0 + lr) * HID + lh * 16;
    const uint32_t dstOff = (uint32_t)lr * ROWB + lh * 32;

    // ---- ldmatrix address offsets (within a tile)
    // A: 16x16 tiles; lanes 0-15 rows, lanes 16-31 rows w/ +8 k-chunk
    const uint32_t offA = (uint32_t)(warp_m * 64 + (lane & 15)) * ROWB
                        + (uint32_t)(lane >> 4) * 16;
    // B: two 8x16 n-tiles per ldmatrix.x4
    const int matb = lane >> 3;
    const uint32_t offB = (uint32_t)(warp_n * 32 + ((matb >> 1) * 8) + (lane & 7)) * ROWB
                        + (uint32_t)(matb & 1) * 16;

    float acc[4][4][4];
#pragma unroll
    for (int i = 0; i < 4; i++)
#pragma unroll
        for (int j = 0; j < 4; j++)
#pragma unroll
            for (int q = 0; q < 4; q++) acc[i][j][q] = 0.f;

    // ---- stage loader
    auto load_stage = [&](int s) {
        const int e  = s >> 6;
        const int k0 = (s & 63) * BK;
        const uint32_t st = sbase + (uint32_t)(s & 1) * STAGE_B + dstOff;
        const __nv_bfloat16* pa = srcAh + k0;
        const __nv_bfloat16* pl = srcAl + k0;
        const __nv_bfloat16* pb = g_wthi + (size_t)e * HID * HID + bRowOff + k0;
        const __nv_bfloat16* pc = g_wtlo + (size_t)e * HID * HID + bRowOff + k0;
        CP16(st,                  pa);     CP16(st + 16,              pa + 8);
        CP16(st + TILE_B,         pl);     CP16(st + TILE_B + 16,     pl + 8);
        CP16(st + 2 * TILE_B,     pb);     CP16(st + 2 * TILE_B + 16, pb + 8);
        CP16(st + 3 * TILE_B,     pc);     CP16(st + 3 * TILE_B + 16, pc + 8);
        CP_COMMIT();
    };

    load_stage(0);

    for (int s = 0; s < TOT_ITERS; s++) {
        if (s + 1 < TOT_ITERS) { load_stage(s + 1); CP_WAIT(1); }
        else                   { CP_WAIT(0); }
        __syncthreads();

        const uint32_t stage = sbase + (uint32_t)(s & 1) * STAGE_B;
#pragma unroll
        for (int ks = 0; ks < 2; ks++) {
            // B fragments: 4 n-tiles, hi and lo
            uint32_t bh[8], bl[8];
            LDSM_X4(bh[0], bh[1], bh[2], bh[3],
                    stage + 2 * TILE_B + offB + ks * 32);
            LDSM_X4(bh[4], bh[5], bh[6], bh[7],
                    stage + 2 * TILE_B + offB + 16 * ROWB + ks * 32);
            LDSM_X4(bl[0], bl[1], bl[2], bl[3],
                    stage + 3 * TILE_B + offB + ks * 32);
            LDSM_X4(bl[4], bl[5], bl[6], bl[7],
                    stage + 3 * TILE_B + offB + 16 * ROWB + ks * 32);
#pragma unroll
            for (int mt = 0; mt < 4; mt++) {
                uint32_t ah[4], al[4];
                LDSM_X4(ah[0], ah[1], ah[2], ah[3],
                        stage + offA + mt * (16 * ROWB) + ks * 32);
                LDSM_X4(al[0], al[1], al[2], al[3],
                        stage + TILE_B + offA + mt * (16 * ROWB) + ks * 32);
#pragma unroll
                for (int nt = 0; nt < 4; nt++) {
                    mma16816(acc[mt][nt], ah, &bh[2 * nt]);
                    mma16816(acc[mt][nt], ah, &bl[2 * nt]);
                    mma16816(acc[mt][nt], al, &bh[2 * nt]);
                }
            }
        }

        if ((s & 63) == 63) {
            // ---- epilogue for expert e
            const int e = s >> 6;
#pragma unroll
            for (int nt = 0; nt < 4; nt++) {
                const int col = f0 + warp_n * 32 + nt * 8 + (lane & 3) * 2;
                const float2 bb = *(const float2*)&bias[(size_t)e * HID + col];
                const float2 cc = *(const float2*)&cached[(size_t)e * HID + col];
#pragma unroll
                for (int mt = 0; mt < 4; mt++) {
                    const int row0 = n0 + warp_m * 64 + mt * 16 + (lane >> 2);
                    const float g0 = g_gate[(size_t)row0 * NE + e];
                    const float g1 = g_gate[(size_t)(row0 + 8) * NE + e];
                    float* p0 = out + (size_t)row0 * HID + col;
                    float* p1 = out + (size_t)(row0 + 8) * HID + col;
                    float2 v0, v1;
                    v0.x = g0 * (fmaxf(acc[mt][nt][0] + bb.x, 0.f) + cc.x);
                    v0.y = g0 * (fmaxf(acc[mt][nt][1] + bb.y, 0.f) + cc.y);
                    v1.x = g1 * (fmaxf(acc[mt][nt][2] + bb.x, 0.f) + cc.x);
                    v1.y = g1 * (fmaxf(acc[mt][nt][3] + bb.y, 0.f) + cc.y);
                    if (e == 0) {
                        *(float2*)p0 = v0;
                        *(float2*)p1 = v1;
                    } else {
                        float2 o0 = *(const float2*)p0;
                        float2 o1 = *(const float2*)p1;
                        o0.x += v0.x; o0.y += v0.y;
                        o1.x += v1.x; o1.y += v1.y;
                        *(float2*)p0 = o0;
                        *(float2*)p1 = o1;
                    }
                    acc[mt][nt][0] = 0.f; acc[mt][nt][1] = 0.f;
                    acc[mt][nt][2] = 0.f; acc[mt][nt][3] = 0.f;
                }
            }
        }
        __syncthreads();   // protect smem buffer reuse by the prefetched load
    }
}

// ---------------------------------------------------------------------------
// Launch
// inputs: x[8192*2048], W[8*2048*2048], b[8*2048], Wg[2048*8], bg[8], cached[8*2048]
// ---------------------------------------------------------------------------
extern "C" void kernel_launch(void* const* d_in, const int* in_sizes, int n_in,
                              void* d_out, int out_size) {
    const float* x      = (const float*)d_in[0];
    const float* W      = (const float*)d_in[1];
    const float* b      = (const float*)d_in[2];
    const float* Wg     = (const float*)d_in[3];
    const float* bg     = (const float*)d_in[4];
    const float* cached = (const float*)d_in[5];
    float* out = (float*)d_out;

    gate_kernel<<<N_TOK / 8, 256>>>(x, Wg, bg);
    split_x_kernel<<<(N_TOK * HID) / (256 * 8), 256>>>(x);
    transpose_split_w<<<dim3(HID / 32, HID / 32, NE), 256>>>(W);

    static bool attr_set = false;
    if (!attr_set) {
        cudaFuncSetAttribute(moe_mma_kernel,
                             cudaFuncAttributeMaxDynamicSharedMemorySize, SMEM_MAIN);
        attr_set = true;
    }
    moe_mma_kernel<<<dim3(HID / 128, N_TOK / 128), 256, SMEM_MAIN>>>(b, cached, out);
}